// round 5
// baseline (speedup 1.0000x reference)
#include <cuda_runtime.h>
#include <cuda_fp16.h>
#include <cstdint>

#define NT    16384
#define HD    1024
#define MD    512
#define NEXP  8

#define BM    128
#define BN    128
#define BK    32
#define NITER (HD / BK)       // 32
#define NSTAGE 3
#define LDS   40              // smem row stride in halves (32 + 8 pad)
#define STG   10240           // bytes per stage per tile (BM*LDS*2)
#define SM_A  0
#define SM_B  (NSTAGE * STG)          // 30720
#define SM_TOK (2 * NSTAGE * STG)     // 61440
#define DYN_SMEM (SM_TOK + 512 + 64)

// ---------------------------------------------------------------------------
// Static device scratch
// ---------------------------------------------------------------------------
__device__ float  g_h[NT * MD];                    // router hidden (fp32)
__device__ __half g_xh[NT * HD];                   // X in fp16
__device__ __half g_w1t[MD * HD];                  // w1^T [n][k] fp16
__device__ __half g_wt[NEXP * HD * HD];            // W^T  [e][n][k] fp16
__device__ int g_eid[NT], g_sorted[NT], g_cnt[NEXP], g_off[NEXP], g_cur[NEXP];

// ---------------------------------------------------------------------------
// PTX helpers (compute_103 baseline: cp.async / ldmatrix / mma.sync)
// ---------------------------------------------------------------------------
__device__ __forceinline__ uint32_t smem_u32(const void* p) {
    uint32_t a;
    asm("{ .reg .u64 t; cvta.to.shared.u64 t, %1; cvt.u32.u64 %0, t; }" : "=r"(a) : "l"(p));
    return a;
}
#define CP16(sm, gm) \
    asm volatile("cp.async.cg.shared.global [%0], [%1], 16;" :: "r"(sm), "l"(gm))
#define CP_COMMIT() asm volatile("cp.async.commit_group;")
#define CP_WAIT1()  asm volatile("cp.async.wait_group 1;")

#define LDM4(r, a) \
    asm volatile("ldmatrix.sync.aligned.m8n8.x4.shared.b16 {%0,%1,%2,%3}, [%4];" \
        : "=r"((r)[0]), "=r"((r)[1]), "=r"((r)[2]), "=r"((r)[3]) : "r"(a))

#define MMA16816(d, a, b0, b1) \
    asm volatile("mma.sync.aligned.m16n8k16.row.col.f32.f16.f16.f32 " \
        "{%0,%1,%2,%3}, {%4,%5,%6,%7}, {%8,%9}, {%0,%1,%2,%3};" \
        : "+f"((d)[0]), "+f"((d)[1]), "+f"((d)[2]), "+f"((d)[3]) \
        : "r"((a)[0]), "r"((a)[1]), "r"((a)[2]), "r"((a)[3]), "r"(b0), "r"(b1))

// ---------------------------------------------------------------------------
// Setup kernels
// ---------------------------------------------------------------------------
__global__ void zero_kernel() {
    int i = threadIdx.x;
    if (i < NEXP) { g_cnt[i] = 0; g_cur[i] = 0; }
}

__global__ __launch_bounds__(256) void convx_kernel(const float* __restrict__ X) {
    size_t base = ((size_t)blockIdx.x * 256 + threadIdx.x) * 8;
    float4 v0 = *(const float4*)(X + base);
    float4 v1 = *(const float4*)(X + base + 4);
    __half2* d = (__half2*)(g_xh + base);
    d[0] = __floats2half2_rn(v0.x, v0.y);
    d[1] = __floats2half2_rn(v0.z, v0.w);
    d[2] = __floats2half2_rn(v1.x, v1.y);
    d[3] = __floats2half2_rn(v1.z, v1.w);
}

// src fp32 [e][HD][ncols] -> dst fp16 [e][n][HD]  (transpose + convert)
__global__ __launch_bounds__(256) void transconv_kernel(
    const float* __restrict__ src, __half* __restrict__ dst, int ncols)
{
    __shared__ float t[32][33];
    int e = blockIdx.z;
    const float* S = src + (size_t)e * HD * ncols;
    __half* D = dst + (size_t)e * HD * ncols;
    int nb = blockIdx.x * 32, kb = blockIdx.y * 32;
    int lx = threadIdx.x & 31, ly = threadIdx.x >> 5;
    #pragma unroll
    for (int i = 0; i < 4; i++)
        t[ly + i * 8][lx] = S[(size_t)(kb + ly + i * 8) * ncols + nb + lx];
    __syncthreads();
    #pragma unroll
    for (int i = 0; i < 4; i++) {
        int n = nb + ly + i * 8, k = kb + lx;
        D[(size_t)n * HD + k] = __float2half_rn(t[lx][ly + i * 8]);
    }
}

// ---------------------------------------------------------------------------
// fp16 mma.sync GEMM, 128x128x32 tile, 8 warps, 3-stage cp.async pipeline,
// one __syncthreads per chunk. A rows optionally gathered via g_sorted.
// ---------------------------------------------------------------------------
template<bool GATHER, bool RELU>
__global__ __launch_bounds__(256) void mma_gemm_kernel(
    const __half* __restrict__ Ag, const __half* __restrict__ Bg,
    const float* __restrict__ bias, float* __restrict__ out,
    int ostride, int npe)
{
    extern __shared__ __align__(16) char smem[];
    int* tokS = (int*)(smem + SM_TOK);

    int tid = threadIdx.x, lane = tid & 31, wid = tid >> 5;
    int e = blockIdx.y;
    int tile0 = blockIdx.z * BM;
    int n0 = blockIdx.x * BN;

    int cnt = NT;
    if (GATHER) {
        cnt = g_cnt[e];
        if (tile0 >= cnt) return;
        int seg = g_off[e];
        if (tid < BM) tokS[tid] = g_sorted[seg + min(tile0 + tid, cnt - 1)];
        __syncthreads();
    }

    // cp.async mapping: 2 x 16B per thread per tile per stage
    int idx0 = tid, idx1 = tid + 256;
    int r0 = idx0 >> 2, c0 = idx0 & 3, r1 = idx1 >> 2, c1 = idx1 & 3;
    int ar0 = GATHER ? tokS[r0] : (tile0 + r0);
    int ar1 = GATHER ? tokS[r1] : (tile0 + r1);
    const __half* gA0 = Ag + (size_t)ar0 * HD + c0 * 8;
    const __half* gA1 = Ag + (size_t)ar1 * HD + c1 * 8;
    const __half* Bbase = Bg + (size_t)e * npe * HD;
    const __half* gB0 = Bbase + (size_t)(n0 + r0) * HD + c0 * 8;
    const __half* gB1 = Bbase + (size_t)(n0 + r1) * HD + c1 * 8;

    uint32_t sAbase = smem_u32(smem) + SM_A;
    uint32_t sBbase = smem_u32(smem) + SM_B;
    uint32_t sA0 = sAbase + (r0 * LDS + c0 * 8) * 2;
    uint32_t sA1 = sAbase + (r1 * LDS + c1 * 8) * 2;
    uint32_t sB0 = sBbase + (r0 * LDS + c0 * 8) * 2;
    uint32_t sB1 = sBbase + (r1 * LDS + c1 * 8) * 2;

    // warp tiling: 2 warps along M (64 rows), 4 along N (32 cols)
    int wm = wid & 1, wn = wid >> 1;
    uint32_t aLd = sAbase + ((wm * 64 + (lane & 15)) * LDS + ((lane >> 4) << 3)) * 2;
    uint32_t bLd = sBbase + ((wn * 32 + (lane & 7) + ((lane & 16) ? 8 : 0)) * LDS
                             + ((lane & 8) ? 8 : 0)) * 2;

    float acc[4][4][4];
    #pragma unroll
    for (int i = 0; i < 4; i++)
        #pragma unroll
        for (int j = 0; j < 4; j++)
            #pragma unroll
            for (int q = 0; q < 4; q++) acc[i][j][q] = 0.f;

    // prologue: prefetch stages 0, 1
    #pragma unroll
    for (int s = 0; s < NSTAGE - 1; s++) {
        uint32_t so = s * STG;
        int ko = s * BK;
        CP16(sA0 + so, gA0 + ko); CP16(sA1 + so, gA1 + ko);
        CP16(sB0 + so, gB0 + ko); CP16(sB1 + so, gB1 + ko);
        CP_COMMIT();
    }

    int buf = 0, pbuf = NSTAGE - 1;
    for (int c = 0; c < NITER; c++) {
        CP_WAIT1();            // stage c resident (<=1 pending group)
        __syncthreads();

        // issue stage c+2 (or empty commit in tail) — overlaps compute below
        if (c + NSTAGE - 1 < NITER) {
            uint32_t so = pbuf * STG;
            int ko = (c + NSTAGE - 1) * BK;
            CP16(sA0 + so, gA0 + ko); CP16(sA1 + so, gA1 + ko);
            CP16(sB0 + so, gB0 + ko); CP16(sB1 + so, gB1 + ko);
        }
        CP_COMMIT();

        uint32_t aB = aLd + buf * STG;
        uint32_t bB = bLd + buf * STG;
        #pragma unroll
        for (int kk = 0; kk < BK; kk += 16) {
            uint32_t ar[4][4], br[2][4];
            #pragma unroll
            for (int mi = 0; mi < 4; mi++)
                LDM4(ar[mi], aB + (mi * 16 * LDS + kk) * 2);
            #pragma unroll
            for (int p = 0; p < 2; p++)
                LDM4(br[p], bB + (p * 16 * LDS + kk) * 2);
            #pragma unroll
            for (int mi = 0; mi < 4; mi++) {
                #pragma unroll
                for (int nj = 0; nj < 4; nj++) {
                    uint32_t b0 = br[nj >> 1][(nj & 1) * 2];
                    uint32_t b1 = br[nj >> 1][(nj & 1) * 2 + 1];
                    MMA16816(acc[mi][nj], ar[mi], b0, b1);
                }
            }
        }
        buf  = (buf  == NSTAGE - 1) ? 0 : buf + 1;
        pbuf = (pbuf == NSTAGE - 1) ? 0 : pbuf + 1;
    }

    // Epilogue: bias add (+relu), scatter rows
    const float* bptr = bias + (size_t)e * npe;
    int qrow = lane >> 2, qcol = (lane & 3) * 2;
    #pragma unroll
    for (int mi = 0; mi < 4; mi++) {
        #pragma unroll
        for (int hf = 0; hf < 2; hf++) {
            int mrow = wm * 64 + mi * 16 + qrow + hf * 8;
            if ((tile0 + mrow) >= cnt) continue;
            int orow = GATHER ? tokS[mrow] : (tile0 + mrow);
            float* orp = out + (size_t)orow * ostride + n0;
            #pragma unroll
            for (int nj = 0; nj < 4; nj++) {
                int coln = wn * 32 + nj * 8 + qcol;
                float2 bv = *(const float2*)(bptr + n0 + coln);
                float2 ov;
                ov.x = acc[mi][nj][hf * 2 + 0] + bv.x;
                ov.y = acc[mi][nj][hf * 2 + 1] + bv.y;
                if (RELU) { ov.x = fmaxf(ov.x, 0.f); ov.y = fmaxf(ov.y, 0.f); }
                *(float2*)(orp + coln) = ov;
            }
        }
    }
}

// ---------------------------------------------------------------------------
// Routing: scores from approx h, argmax; near-ties recomputed exactly in fp32
// ---------------------------------------------------------------------------
#define TAU 1e-2f
__global__ __launch_bounds__(256) void route_kernel(
    const float* __restrict__ X,  const float* __restrict__ w1,
    const float* __restrict__ b1, const float* __restrict__ w2,
    const float* __restrict__ b2)
{
    __shared__ float w2s[MD * NEXP];
    for (int i = threadIdx.x; i < MD * NEXP; i += 256) w2s[i] = w2[i];
    __syncthreads();

    int warp = threadIdx.x >> 5, lane = threadIdx.x & 31;
    int t = blockIdx.x * 8 + warp;
    const float* hrow = &g_h[(size_t)t * MD];

    float s[NEXP];
    #pragma unroll
    for (int e = 0; e < NEXP; e++) s[e] = 0.f;
    for (int m = lane; m < MD; m += 32) {
        float hv = hrow[m];
        #pragma unroll
        for (int e = 0; e < NEXP; e++) s[e] += hv * w2s[m * NEXP + e];
    }
    #pragma unroll
    for (int o = 16; o > 0; o >>= 1)
        #pragma unroll
        for (int e = 0; e < NEXP; e++)
            s[e] += __shfl_xor_sync(0xffffffff, s[e], o);

    int need = 0, best = 0;
    if (lane == 0) {
        float v1 = -1e30f, v2 = -1e30f;
        #pragma unroll
        for (int e = 0; e < NEXP; e++) {
            float v = s[e] + b2[e];
            if (v > v1) { v2 = v1; v1 = v; best = e; }
            else if (v > v2) v2 = v;
        }
        need = (v1 - v2 < TAU) ? 1 : 0;
    }
    need = __shfl_sync(0xffffffff, need, 0);

    if (need) {
        float hl[16];
        #pragma unroll
        for (int j = 0; j < 16; j++) hl[j] = b1[lane * 16 + j];
        const float* xr = &X[(size_t)t * HD];
        for (int k = 0; k < HD; k++) {
            float xv = xr[k];
            const float* wr = &w1[(size_t)k * MD + lane * 16];
            #pragma unroll
            for (int j = 0; j < 16; j++) hl[j] += xv * wr[j];
        }
        float sr[NEXP];
        #pragma unroll
        for (int e = 0; e < NEXP; e++) sr[e] = 0.f;
        #pragma unroll
        for (int j = 0; j < 16; j++) {
            float hv = fmaxf(hl[j], 0.f);
            const float* wc = &w2s[(lane * 16 + j) * NEXP];
            #pragma unroll
            for (int e = 0; e < NEXP; e++) sr[e] += hv * wc[e];
        }
        #pragma unroll
        for (int o = 16; o > 0; o >>= 1)
            #pragma unroll
            for (int e = 0; e < NEXP; e++)
                sr[e] += __shfl_xor_sync(0xffffffff, sr[e], o);
        if (lane == 0) {
            float bv = sr[0] + b2[0]; best = 0;
            #pragma unroll
            for (int e = 1; e < NEXP; e++) {
                float v = sr[e] + b2[e];
                if (v > bv) { bv = v; best = e; }
            }
        }
    }
    if (lane == 0) {
        g_eid[t] = best;
        atomicAdd(&g_cnt[best], 1);
    }
}

__global__ void prefix_kernel() {
    if (threadIdx.x == 0) {
        int o = 0;
        for (int e = 0; e < NEXP; e++) { g_off[e] = o; o += g_cnt[e]; }
    }
}
__global__ void scatter_kernel(int ntok) {
    int t = blockIdx.x * 256 + threadIdx.x;
    if (t >= ntok) return;
    int e = g_eid[t];
    int pos = g_off[e] + atomicAdd(&g_cur[e], 1);
    g_sorted[pos] = t;
}

// ---------------------------------------------------------------------------
extern "C" void kernel_launch(void* const* d_in, const int* in_sizes, int n_in,
                              void* d_out, int out_size)
{
    const float* X  = (const float*)d_in[0];
    const float* w1 = (const float*)d_in[1];
    const float* b1 = (const float*)d_in[2];
    const float* w2 = (const float*)d_in[3];
    const float* b2 = (const float*)d_in[4];
    const float* eW = (const float*)d_in[5];
    const float* eb = (const float*)d_in[6];
    float* out = (float*)d_out;

    static int attr_done = 0;
    if (!attr_done) {
        cudaFuncSetAttribute(mma_gemm_kernel<false, true>,
                             cudaFuncAttributeMaxDynamicSharedMemorySize, DYN_SMEM);
        cudaFuncSetAttribute(mma_gemm_kernel<true, false>,
                             cudaFuncAttributeMaxDynamicSharedMemorySize, DYN_SMEM);
        attr_done = 1;
    }

    __half *xh, *w1t, *wt;
    float* hbuf;
    cudaGetSymbolAddress((void**)&xh,   g_xh);
    cudaGetSymbolAddress((void**)&w1t,  g_w1t);
    cudaGetSymbolAddress((void**)&wt,   g_wt);
    cudaGetSymbolAddress((void**)&hbuf, g_h);

    zero_kernel<<<1, 32>>>();
    convx_kernel<<<NT * HD / 2048, 256>>>(X);
    transconv_kernel<<<dim3(MD / 32, HD / 32, 1), 256>>>(w1, w1t, MD);
    transconv_kernel<<<dim3(HD / 32, HD / 32, NEXP), 256>>>(eW, wt, HD);

    mma_gemm_kernel<false, true><<<dim3(MD / BN, 1, NT / BM), 256, DYN_SMEM>>>(
        xh, w1t, b1, hbuf, MD, MD);

    route_kernel<<<NT / 8, 256>>>(X, w1, b1, w2, b2);
    prefix_kernel<<<1, 32>>>();
    scatter_kernel<<<(NT + 255) / 256, 256>>>(NT);

    mma_gemm_kernel<true, false><<<dim3(HD / BN, NEXP, NT / BM), 256, DYN_SMEM>>>(
        xh, wt, eb, out, HD, HD);
}